// round 2
// baseline (speedup 1.0000x reference)
#include <cuda_runtime.h>
#include <cuda_bf16.h>

#define Bb 16
#define Hh 12
#define Nn 784
#define NN (Nn * Nn)            // 614656
#define NN4 (NN / 4)            // 153664 float4 per batch
#define N4 (Nn / 4)             // 196 float4 per row

__device__ float g_max[Bb];
__device__ float g_sum[Bb];

__global__ void init_kernel() {
    int t = threadIdx.x;
    if (t < Bb) { g_max[t] = 0.0f; g_sum[t] = 0.0f; }
}

// One CTA per (b, i): load 12 head-rows to SMEM, compute rowsums, write
// agg[b,i,:] = sum_h m[b,h,i,:] * rowsum_h, and atomicMax the batch max.
__global__ __launch_bounds__(256) void agg_kernel(const float* __restrict__ m,
                                                  float* __restrict__ out) {
    __shared__ float tiles[Hh * Nn];     // [h][l], 37632 B
    __shared__ float rowsum[Hh];
    __shared__ float warpmax[8];

    const int i = blockIdx.x;   // 0..783
    const int b = blockIdx.y;   // 0..15
    const int tid = threadIdx.x;
    const int wid = tid >> 5;
    const int lane = tid & 31;

    // ---- load 12 x 784 floats (vectorized) ----
    for (int idx = tid; idx < Hh * N4; idx += 256) {
        const int h = idx / N4;
        const int c = idx - h * N4;
        const float4* src = (const float4*)m +
            ((size_t)(b * Hh + h) * Nn + i) * (size_t)N4;
        ((float4*)tiles)[idx] = src[c];
    }
    __syncthreads();

    // ---- per-head rowsum: warp w handles heads w, w+8 ----
    for (int h = wid; h < Hh; h += 8) {
        float s = 0.0f;
        const float* row = tiles + h * Nn;
        for (int l = lane; l < Nn; l += 32) s += row[l];
        #pragma unroll
        for (int off = 16; off > 0; off >>= 1)
            s += __shfl_xor_sync(0xFFFFFFFFu, s, off);
        if (lane == 0) rowsum[h] = s;
    }
    __syncthreads();

    float rs[Hh];
    #pragma unroll
    for (int h = 0; h < Hh; h++) rs[h] = rowsum[h];

    // ---- weighted head-sum, write out, track max ----
    float4* dst = (float4*)out + (size_t)b * NN4 + (size_t)i * N4;
    float lmax = 0.0f;
    for (int c = tid; c < N4; c += 256) {
        float4 acc = make_float4(0.f, 0.f, 0.f, 0.f);
        #pragma unroll
        for (int h = 0; h < Hh; h++) {
            float4 v = ((const float4*)tiles)[h * N4 + c];
            acc.x += v.x * rs[h];
            acc.y += v.y * rs[h];
            acc.z += v.z * rs[h];
            acc.w += v.w * rs[h];
        }
        dst[c] = acc;
        lmax = fmaxf(lmax, fmaxf(fmaxf(acc.x, acc.y), fmaxf(acc.z, acc.w)));
    }

    // ---- block max -> per-batch atomicMax (all values >= 0) ----
    #pragma unroll
    for (int off = 16; off > 0; off >>= 1)
        lmax = fmaxf(lmax, __shfl_xor_sync(0xFFFFFFFFu, lmax, off));
    if (lane == 0) warpmax[wid] = lmax;
    __syncthreads();
    if (tid == 0) {
        float mx = warpmax[0];
        #pragma unroll
        for (int w = 1; w < 8; w++) mx = fmaxf(mx, warpmax[w]);
        atomicMax((int*)&g_max[b], __float_as_int(mx));
    }
}

// Sum of exp(x - max) per batch.
__global__ __launch_bounds__(256) void expsum_kernel(const float* __restrict__ out) {
    __shared__ float warpsum[8];
    const int b = blockIdx.y;
    const float mx = g_max[b];
    const float4* p = (const float4*)out + (size_t)b * NN4;

    float s = 0.0f;
    for (int c = blockIdx.x * 256 + threadIdx.x; c < NN4; c += gridDim.x * 256) {
        float4 v = p[c];
        s += __expf(v.x - mx) + __expf(v.y - mx) +
             __expf(v.z - mx) + __expf(v.w - mx);
    }
    #pragma unroll
    for (int off = 16; off > 0; off >>= 1)
        s += __shfl_xor_sync(0xFFFFFFFFu, s, off);
    const int wid = threadIdx.x >> 5, lane = threadIdx.x & 31;
    if (lane == 0) warpsum[wid] = s;
    __syncthreads();
    if (threadIdx.x == 0) {
        float t = warpsum[0];
        #pragma unroll
        for (int w = 1; w < 8; w++) t += warpsum[w];
        atomicAdd(&g_sum[b], t);
    }
}

// Normalize in place: out = exp(x - max) / sum.
__global__ __launch_bounds__(256) void norm_kernel(float* __restrict__ out) {
    const int b = blockIdx.y;
    const float mx = g_max[b];
    const float inv = 1.0f / g_sum[b];
    float4* p = (float4*)out + (size_t)b * NN4;

    for (int c = blockIdx.x * 256 + threadIdx.x; c < NN4; c += gridDim.x * 256) {
        float4 v = p[c];
        v.x = __expf(v.x - mx) * inv;
        v.y = __expf(v.y - mx) * inv;
        v.z = __expf(v.z - mx) * inv;
        v.w = __expf(v.w - mx) * inv;
        p[c] = v;
    }
}

extern "C" void kernel_launch(void* const* d_in, const int* in_sizes, int n_in,
                              void* d_out, int out_size) {
    const float* m = (const float*)d_in[0];
    float* out = (float*)d_out;

    init_kernel<<<1, 32>>>();

    dim3 g1(Nn, Bb);            // 784 x 16 CTAs
    agg_kernel<<<g1, 256>>>(m, out);

    dim3 g2(256, Bb);           // 256 blocks per batch
    expsum_kernel<<<g2, 256>>>(out);
    norm_kernel<<<g2, 256>>>(out);
}

// round 3
// speedup vs baseline: 1.3681x; 1.3681x over previous
#include <cuda_runtime.h>
#include <cuda_bf16.h>

#define Bb 16
#define Hh 12
#define Nn 784
#define NN (Nn * Nn)            // 614656
#define NN4 (NN / 4)            // 153664 float4 per batch
#define NN2 (NN / 2)            // 307328 float2 per batch
#define N4 (Nn / 4)             // 196 float4 per row
#define N2 (Nn / 2)             // 392 float2 per row

__device__ float g_max[Bb];
__device__ float g_sum[Bb];

__global__ void init_kernel() {
    int t = threadIdx.x;
    if (t < Bb) { g_max[t] = 0.0f; g_sum[t] = 0.0f; }
}

// One CTA per (b, i). 12 warps, warp h owns head h:
//  - loads row m[b,h,i,:] (196 float4) with unrolled, division-free addressing
//  - accumulates the rowsum in registers DURING the load (no SMEM re-read)
//  - stages the tile to SMEM once
// Then all 384 threads compute agg[b,i,:] = sum_h tile[h][:] * rowsum[h].
__global__ __launch_bounds__(384) void agg_kernel(const float* __restrict__ m,
                                                  float* __restrict__ out) {
    __shared__ float tiles[Hh * Nn];     // 37632 B
    __shared__ float rowsum[Hh];
    __shared__ float warpmax[12];

    const int i = blockIdx.x;   // 0..783
    const int b = blockIdx.y;   // 0..15
    const int tid  = threadIdx.x;
    const int wid  = tid >> 5;  // == head index, 0..11
    const int lane = tid & 31;

    // ---- phase 1: load + fused rowsum (warp wid -> head wid) ----
    {
        const float4* __restrict__ src = (const float4*)m +
            ((size_t)(b * Hh + wid) * Nn + i) * (size_t)N4;
        float4* __restrict__ stile = (float4*)tiles + wid * N4;

        float s = 0.0f;
        #pragma unroll
        for (int k = 0; k < 6; k++) {
            float4 v = src[lane + 32 * k];
            stile[lane + 32 * k] = v;
            s += (v.x + v.y) + (v.z + v.w);
        }
        if (lane < 4) {                       // 196 = 6*32 + 4
            float4 v = src[192 + lane];
            stile[192 + lane] = v;
            s += (v.x + v.y) + (v.z + v.w);
        }
        #pragma unroll
        for (int off = 16; off > 0; off >>= 1)
            s += __shfl_xor_sync(0xFFFFFFFFu, s, off);
        if (lane == 0) rowsum[wid] = s;
    }
    __syncthreads();

    float rs[Hh];
    #pragma unroll
    for (int h = 0; h < Hh; h++) rs[h] = rowsum[h];

    // ---- phase 2: weighted head-sum at float2 granularity ----
    float2* __restrict__ dst = (float2*)out + (size_t)b * NN2 + (size_t)i * N2;
    float lmax = 0.0f;
    for (int c = tid; c < N2; c += 384) {     // 392 float2 columns
        float2 acc = make_float2(0.f, 0.f);
        #pragma unroll
        for (int h = 0; h < Hh; h++) {
            float2 v = ((const float2*)tiles)[h * N2 + c];
            acc.x += v.x * rs[h];
            acc.y += v.y * rs[h];
        }
        dst[c] = acc;
        lmax = fmaxf(lmax, fmaxf(acc.x, acc.y));
    }

    // ---- block max -> per-batch atomicMax (all values >= 0) ----
    #pragma unroll
    for (int off = 16; off > 0; off >>= 1)
        lmax = fmaxf(lmax, __shfl_xor_sync(0xFFFFFFFFu, lmax, off));
    if (lane == 0) warpmax[wid] = lmax;
    __syncthreads();
    if (tid == 0) {
        float mx = warpmax[0];
        #pragma unroll
        for (int w = 1; w < 12; w++) mx = fmaxf(mx, warpmax[w]);
        atomicMax((int*)&g_max[b], __float_as_int(mx));
    }
}

// Sum of exp(x - max) per batch.
__global__ __launch_bounds__(256) void expsum_kernel(const float* __restrict__ out) {
    __shared__ float warpsum[8];
    const int b = blockIdx.y;
    const float mx = g_max[b];
    const float4* p = (const float4*)out + (size_t)b * NN4;

    float s = 0.0f;
    for (int c = blockIdx.x * 256 + threadIdx.x; c < NN4; c += gridDim.x * 256) {
        float4 v = p[c];
        s += __expf(v.x - mx) + __expf(v.y - mx) +
             __expf(v.z - mx) + __expf(v.w - mx);
    }
    #pragma unroll
    for (int off = 16; off > 0; off >>= 1)
        s += __shfl_xor_sync(0xFFFFFFFFu, s, off);
    const int wid = threadIdx.x >> 5, lane = threadIdx.x & 31;
    if (lane == 0) warpsum[wid] = s;
    __syncthreads();
    if (threadIdx.x == 0) {
        float t = warpsum[0];
        #pragma unroll
        for (int w = 1; w < 8; w++) t += warpsum[w];
        atomicAdd(&g_sum[b], t);
    }
}

// Normalize in place: out = exp(x - max) / sum.
__global__ __launch_bounds__(256) void norm_kernel(float* __restrict__ out) {
    const int b = blockIdx.y;
    const float mx = g_max[b];
    const float inv = 1.0f / g_sum[b];
    float4* p = (float4*)out + (size_t)b * NN4;

    for (int c = blockIdx.x * 256 + threadIdx.x; c < NN4; c += gridDim.x * 256) {
        float4 v = p[c];
        v.x = __expf(v.x - mx) * inv;
        v.y = __expf(v.y - mx) * inv;
        v.z = __expf(v.z - mx) * inv;
        v.w = __expf(v.w - mx) * inv;
        p[c] = v;
    }
}

extern "C" void kernel_launch(void* const* d_in, const int* in_sizes, int n_in,
                              void* d_out, int out_size) {
    const float* m = (const float*)d_in[0];
    float* out = (float*)d_out;

    init_kernel<<<1, 32>>>();

    dim3 g1(Nn, Bb);            // 784 x 16 CTAs
    agg_kernel<<<g1, 384>>>(m, out);

    dim3 g2(256, Bb);           // 256 blocks per batch
    expsum_kernel<<<g2, 256>>>(out);
    norm_kernel<<<g2, 256>>>(out);
}

// round 4
// speedup vs baseline: 1.3854x; 1.0127x over previous
#include <cuda_runtime.h>
#include <cuda_bf16.h>

#define Bb 16
#define Hh 12
#define Nn 784
#define NN (Nn * Nn)            // 614656
#define NN4 (NN / 4)            // 153664 float4 per batch
#define NN2 (NN / 2)            // 307328 float2 per batch
#define N4 (Nn / 4)             // 196 float4 per row
#define N2 (Nn / 2)             // 392 float2 per row

__device__ float g_max[Bb];                 // per-batch global max (atomicMax)
__device__ float g_rowmax[Bb * Nn];         // per-row max m_i
__device__ float g_rowsum[Bb * Nn];         // per-row sum of exp(x - m_i)
__device__ float g_scale[Bb * Nn];          // per-row final scale exp(m_i - M)/S

__global__ void init_kernel() {
    int t = threadIdx.x;
    if (t < Bb) g_max[t] = 0.0f;
}

// One CTA per (b, i). 12 warps, warp h owns head h:
//  phase 1: load row m[b,h,i,:], fused rowsum during load, stage tile to SMEM.
//  phase 2: x[l] = sum_h tile[h][l]*rowsum[h] (in regs), row max m_i,
//           write exp(x - m_i) to out, row sum s_i, atomicMax global max.
__global__ __launch_bounds__(384) void agg_kernel(const float* __restrict__ m,
                                                  float* __restrict__ out) {
    __shared__ float tiles[Hh * Nn];     // 37632 B
    __shared__ float rowsum[Hh];
    __shared__ float wred[12];
    __shared__ float s_bcast;

    const int i = blockIdx.x;   // 0..783
    const int b = blockIdx.y;   // 0..15
    const int tid  = threadIdx.x;
    const int wid  = tid >> 5;  // head index 0..11
    const int lane = tid & 31;

    // ---- phase 1: load + fused per-head rowsum ----
    {
        const float4* __restrict__ src = (const float4*)m +
            ((size_t)(b * Hh + wid) * Nn + i) * (size_t)N4;
        float4* __restrict__ stile = (float4*)tiles + wid * N4;

        float s = 0.0f;
        #pragma unroll
        for (int k = 0; k < 6; k++) {
            float4 v = src[lane + 32 * k];
            stile[lane + 32 * k] = v;
            s += (v.x + v.y) + (v.z + v.w);
        }
        if (lane < 4) {                       // 196 = 6*32 + 4
            float4 v = src[192 + lane];
            stile[192 + lane] = v;
            s += (v.x + v.y) + (v.z + v.w);
        }
        #pragma unroll
        for (int off = 16; off > 0; off >>= 1)
            s += __shfl_xor_sync(0xFFFFFFFFu, s, off);
        if (lane == 0) rowsum[wid] = s;
    }
    __syncthreads();

    float rs[Hh];
    #pragma unroll
    for (int h = 0; h < Hh; h++) rs[h] = rowsum[h];

    // ---- phase 2a: weighted head-sum into registers ----
    const bool has2 = (tid < N2 - 384);       // tid < 8
    float2 v0, v1 = make_float2(0.f, 0.f);
    float lmax = 0.0f;                        // all values >= 0
    {
        float2 acc = make_float2(0.f, 0.f);
        #pragma unroll
        for (int h = 0; h < Hh; h++) {
            float2 t = ((const float2*)tiles)[h * N2 + tid];
            acc.x += t.x * rs[h];
            acc.y += t.y * rs[h];
        }
        v0 = acc;
        lmax = fmaxf(acc.x, acc.y);
    }
    if (has2) {
        float2 acc = make_float2(0.f, 0.f);
        const int c = tid + 384;
        #pragma unroll
        for (int h = 0; h < Hh; h++) {
            float2 t = ((const float2*)tiles)[h * N2 + c];
            acc.x += t.x * rs[h];
            acc.y += t.y * rs[h];
        }
        v1 = acc;
        lmax = fmaxf(lmax, fmaxf(acc.x, acc.y));
    }

    // ---- row max reduce ----
    #pragma unroll
    for (int off = 16; off > 0; off >>= 1)
        lmax = fmaxf(lmax, __shfl_xor_sync(0xFFFFFFFFu, lmax, off));
    if (lane == 0) wred[wid] = lmax;
    __syncthreads();
    if (tid == 0) {
        float mx = wred[0];
        #pragma unroll
        for (int w = 1; w < 12; w++) mx = fmaxf(mx, wred[w]);
        s_bcast = mx;
    }
    __syncthreads();
    const float m_i = s_bcast;

    // ---- exp, store, row sum ----
    float2* __restrict__ dst = (float2*)out + (size_t)b * NN2 + (size_t)i * N2;
    float lsum;
    {
        float ex = __expf(v0.x - m_i);
        float ey = __expf(v0.y - m_i);
        dst[tid] = make_float2(ex, ey);
        lsum = ex + ey;
    }
    if (has2) {
        float ex = __expf(v1.x - m_i);
        float ey = __expf(v1.y - m_i);
        dst[tid + 384] = make_float2(ex, ey);
        lsum += ex + ey;
    }
    #pragma unroll
    for (int off = 16; off > 0; off >>= 1)
        lsum += __shfl_xor_sync(0xFFFFFFFFu, lsum, off);
    if (lane == 0) wred[wid] = lsum;
    __syncthreads();
    if (tid == 0) {
        float ssum = wred[0];
        #pragma unroll
        for (int w = 1; w < 12; w++) ssum += wred[w];
        const int r = b * Nn + i;
        g_rowmax[r] = m_i;
        g_rowsum[r] = ssum;
        atomicMax((int*)&g_max[b], __float_as_int(m_i));
    }
}

// One block per batch: S = sum_i s_i * exp(m_i - M); scale_i = exp(m_i - M)/S.
__global__ __launch_bounds__(256) void mid_kernel() {
    __shared__ float wred[8];
    __shared__ float s_inv;
    const int b = blockIdx.x;
    const float M = g_max[b];
    const int tid = threadIdx.x;

    float s = 0.0f;
    for (int i = tid; i < Nn; i += 256)
        s += g_rowsum[b * Nn + i] * __expf(g_rowmax[b * Nn + i] - M);
    #pragma unroll
    for (int off = 16; off > 0; off >>= 1)
        s += __shfl_xor_sync(0xFFFFFFFFu, s, off);
    const int wid = tid >> 5, lane = tid & 31;
    if (lane == 0) wred[wid] = s;
    __syncthreads();
    if (tid == 0) {
        float t = wred[0];
        #pragma unroll
        for (int w = 1; w < 8; w++) t += wred[w];
        s_inv = 1.0f / t;
    }
    __syncthreads();
    const float inv = s_inv;
    for (int i = tid; i < Nn; i += 256)
        g_scale[b * Nn + i] = __expf(g_rowmax[b * Nn + i] - M) * inv;
}

// Block per 2 rows: out *= scale[row]. Pure streaming multiply, no exps.
__global__ __launch_bounds__(256) void norm_kernel(float* __restrict__ out) {
    const int b = blockIdx.y;
    const int r0 = blockIdx.x * 2;            // rows r0, r0+1
    const float s0 = g_scale[b * Nn + r0];
    const float s1 = g_scale[b * Nn + r0 + 1];

    float4* p = (float4*)out + (size_t)b * NN4 + (size_t)r0 * N4;
    const int tid = threadIdx.x;

    // 2 rows = 392 float4; iteration 1: c=tid (<256), iteration 2: c=tid+256 (<392)
    {
        const float sc = (tid < N4) ? s0 : s1;
        float4 v = p[tid];
        v.x *= sc; v.y *= sc; v.z *= sc; v.w *= sc;
        p[tid] = v;
    }
    if (tid < 392 - 256) {
        const int c = tid + 256;
        const float sc = (c < N4) ? s0 : s1;  // always s1 here (c >= 256 > 196)
        float4 v = p[c];
        v.x *= sc; v.y *= sc; v.z *= sc; v.w *= sc;
        p[c] = v;
    }
}

extern "C" void kernel_launch(void* const* d_in, const int* in_sizes, int n_in,
                              void* d_out, int out_size) {
    const float* m = (const float*)d_in[0];
    float* out = (float*)d_out;

    init_kernel<<<1, 32>>>();

    dim3 g1(Nn, Bb);            // 784 x 16 CTAs
    agg_kernel<<<g1, 384>>>(m, out);

    mid_kernel<<<Bb, 256>>>();

    dim3 g3(Nn / 2, Bb);        // 392 x 16 blocks, 2 rows each
    norm_kernel<<<g3, 256>>>(out);
}

// round 6
// speedup vs baseline: 1.4132x; 1.0200x over previous
#include <cuda_runtime.h>
#include <cuda_fp16.h>
#include <cuda_bf16.h>

#define Bb 16
#define Hh 12
#define Nn 784
#define NN (Nn * Nn)            // 614656
#define NN4 (NN / 4)            // 153664 float4 per batch
#define NN2 (NN / 2)            // 307328 float2/half2 per batch
#define N4 (Nn / 4)             // 196 float4 per row
#define N2 (Nn / 2)             // 392 float2/half2 per row

__device__ float g_max[Bb];                 // per-batch global max (atomicMax)
__device__ float g_rowmax[Bb * Nn];         // per-row max m_i
__device__ float g_rowsum[Bb * Nn];         // per-row sum of exp(x - m_i) (fp32)
__device__ float g_scale[Bb * Nn];          // per-row final scale exp(m_i - M)/S
__device__ __half2 g_exp[Bb * NN2];         // fp16 scratch: exp(x - m_i), 19.7 MB

__global__ void init_kernel() {
    int t = threadIdx.x;
    if (t < Bb) g_max[t] = 0.0f;
}

// One CTA per (b, i). 12 warps, warp h owns head h:
//  phase 1: load row m[b,h,i,:], fused rowsum during load, stage tile to SMEM.
//  phase 2: x[l] = sum_h tile[h][l]*rowsum[h] (in regs), row max m_i,
//           write fp16 exp(x - m_i) to scratch, fp32 row sum s_i, atomicMax.
__global__ __launch_bounds__(384) void agg_kernel(const float* __restrict__ m) {
    __shared__ float tiles[Hh * Nn];     // 37632 B
    __shared__ float rowsum[Hh];
    __shared__ float wred[12];
    __shared__ float s_bcast;

    const int i = blockIdx.x;   // 0..783
    const int b = blockIdx.y;   // 0..15
    const int tid  = threadIdx.x;
    const int wid  = tid >> 5;  // head index 0..11
    const int lane = tid & 31;

    // ---- phase 1: load + fused per-head rowsum ----
    {
        const float4* __restrict__ src = (const float4*)m +
            ((size_t)(b * Hh + wid) * Nn + i) * (size_t)N4;
        float4* __restrict__ stile = (float4*)tiles + wid * N4;

        float s = 0.0f;
        #pragma unroll
        for (int k = 0; k < 6; k++) {
            float4 v = src[lane + 32 * k];
            stile[lane + 32 * k] = v;
            s += (v.x + v.y) + (v.z + v.w);
        }
        if (lane < 4) {                       // 196 = 6*32 + 4
            float4 v = src[192 + lane];
            stile[192 + lane] = v;
            s += (v.x + v.y) + (v.z + v.w);
        }
        #pragma unroll
        for (int off = 16; off > 0; off >>= 1)
            s += __shfl_xor_sync(0xFFFFFFFFu, s, off);
        if (lane == 0) rowsum[wid] = s;
    }
    __syncthreads();

    float rs[Hh];
    #pragma unroll
    for (int h = 0; h < Hh; h++) rs[h] = rowsum[h];

    // ---- phase 2a: weighted head-sum into registers ----
    const bool has2 = (tid < N2 - 384);       // tid < 8
    float2 v0, v1 = make_float2(0.f, 0.f);
    float lmax = 0.0f;                        // all values >= 0
    {
        float2 acc = make_float2(0.f, 0.f);
        #pragma unroll
        for (int h = 0; h < Hh; h++) {
            float2 t = ((const float2*)tiles)[h * N2 + tid];
            acc.x += t.x * rs[h];
            acc.y += t.y * rs[h];
        }
        v0 = acc;
        lmax = fmaxf(acc.x, acc.y);
    }
    if (has2) {
        float2 acc = make_float2(0.f, 0.f);
        const int c = tid + 384;
        #pragma unroll
        for (int h = 0; h < Hh; h++) {
            float2 t = ((const float2*)tiles)[h * N2 + c];
            acc.x += t.x * rs[h];
            acc.y += t.y * rs[h];
        }
        v1 = acc;
        lmax = fmaxf(lmax, fmaxf(acc.x, acc.y));
    }

    // ---- row max reduce ----
    #pragma unroll
    for (int off = 16; off > 0; off >>= 1)
        lmax = fmaxf(lmax, __shfl_xor_sync(0xFFFFFFFFu, lmax, off));
    if (lane == 0) wred[wid] = lmax;
    __syncthreads();
    if (tid == 0) {
        float mx = wred[0];
        #pragma unroll
        for (int w = 1; w < 12; w++) mx = fmaxf(mx, wred[w]);
        s_bcast = mx;
    }
    __syncthreads();
    const float m_i = s_bcast;

    // ---- exp, fp16 store, fp32 row sum ----
    __half2* __restrict__ dst = g_exp + (size_t)b * NN2 + (size_t)i * N2;
    float lsum;
    {
        float ex = __expf(v0.x - m_i);
        float ey = __expf(v0.y - m_i);
        dst[tid] = __floats2half2_rn(ex, ey);
        lsum = ex + ey;
    }
    if (has2) {
        float ex = __expf(v1.x - m_i);
        float ey = __expf(v1.y - m_i);
        dst[tid + 384] = __floats2half2_rn(ex, ey);
        lsum += ex + ey;
    }
    #pragma unroll
    for (int off = 16; off > 0; off >>= 1)
        lsum += __shfl_xor_sync(0xFFFFFFFFu, lsum, off);
    if (lane == 0) wred[wid] = lsum;
    __syncthreads();
    if (tid == 0) {
        float ssum = wred[0];
        #pragma unroll
        for (int w = 1; w < 12; w++) ssum += wred[w];
        const int r = b * Nn + i;
        g_rowmax[r] = m_i;
        g_rowsum[r] = ssum;
        atomicMax((int*)&g_max[b], __float_as_int(m_i));
    }
}

// One block per batch: S = sum_i s_i * exp(m_i - M); scale_i = exp(m_i - M)/S.
__global__ __launch_bounds__(256) void mid_kernel() {
    __shared__ float wred[8];
    __shared__ float s_inv;
    const int b = blockIdx.x;
    const float M = g_max[b];
    const int tid = threadIdx.x;

    float s = 0.0f;
    for (int i = tid; i < Nn; i += 256)
        s += g_rowsum[b * Nn + i] * __expf(g_rowmax[b * Nn + i] - M);
    #pragma unroll
    for (int off = 16; off > 0; off >>= 1)
        s += __shfl_xor_sync(0xFFFFFFFFu, s, off);
    const int wid = tid >> 5, lane = tid & 31;
    if (lane == 0) wred[wid] = s;
    __syncthreads();
    if (tid == 0) {
        float t = wred[0];
        #pragma unroll
        for (int w = 1; w < 8; w++) t += wred[w];
        s_inv = 1.0f / t;
    }
    __syncthreads();
    const float inv = s_inv;
    for (int i = tid; i < Nn; i += 256)
        g_scale[b * Nn + i] = __expf(g_rowmax[b * Nn + i] - M) * inv;
}

// Block per 2 rows: out[l] = half2float(exp_scratch[l]) * scale[row].
// Reads 19.7MB fp16, writes 39MB fp32.
__global__ __launch_bounds__(256) void norm_kernel(float* __restrict__ out) {
    const int b = blockIdx.y;
    const int r0 = blockIdx.x * 2;            // rows r0, r0+1
    const float s0 = g_scale[b * Nn + r0];
    const float s1 = g_scale[b * Nn + r0 + 1];

    const __half2* __restrict__ src = g_exp + (size_t)b * NN2 + (size_t)r0 * N2;
    float4* __restrict__ p = (float4*)out + (size_t)b * NN4 + (size_t)r0 * N4;
    const int tid = threadIdx.x;

    // 2 rows = 392 float4 outputs; each thread converts 2 half2 -> 1 float4.
    {
        const float sc = (tid < N4) ? s0 : s1;
        float2 a = __half22float2(src[2 * tid]);
        float2 c = __half22float2(src[2 * tid + 1]);
        p[tid] = make_float4(a.x * sc, a.y * sc, c.x * sc, c.y * sc);
    }
    if (tid < 392 - 256) {
        const int c4 = tid + 256;             // 256..391, always row r0+1
        float2 a = __half22float2(src[2 * c4]);
        float2 c = __half22float2(src[2 * c4 + 1]);
        p[c4] = make_float4(a.x * s1, a.y * s1, c.x * s1, c.y * s1);
    }
}

extern "C" void kernel_launch(void* const* d_in, const int* in_sizes, int n_in,
                              void* d_out, int out_size) {
    const float* m = (const float*)d_in[0];
    float* out = (float*)d_out;

    init_kernel<<<1, 32>>>();

    dim3 g1(Nn, Bb);            // 784 x 16 CTAs
    agg_kernel<<<g1, 384>>>(m);

    mid_kernel<<<Bb, 256>>>();

    dim3 g3(Nn / 2, Bb);        // 392 x 16 blocks, 2 rows each
    norm_kernel<<<g3, 256>>>(out);
}